// round 14
// baseline (speedup 1.0000x reference)
#include <cuda_runtime.h>
#include <cuda_bf16.h>
#include <math.h>
#include <stdint.h>

#define Nn0 2000
#define Nn1 6000
#define Nn2 4000
#define CC  128

// ================= static scratch (no allocation) =================
__device__ float g_h0[Nn0 * CC];
__device__ float g_h1[Nn1 * CC];
__device__ float g_h2[Nn2 * CC];

__device__ float g_part[24 * 1024 * 1024];   // fp32 partial pool (96MB)

// operators bf16 hi/lo
__device__ __nv_bfloat16 g_L0h[Nn0 * Nn0],  g_L0l[Nn0 * Nn0];
__device__ __nv_bfloat16 g_L1dh[Nn1 * Nn1], g_L1dl[Nn1 * Nn1];
__device__ __nv_bfloat16 g_L1uh[Nn1 * Nn1], g_L1ul[Nn1 * Nn1];
__device__ __nv_bfloat16 g_B1h[Nn0 * Nn1],  g_B1l[Nn0 * Nn1];
__device__ __nv_bfloat16 g_B1th[Nn1 * Nn0], g_B1tl[Nn1 * Nn0];
__device__ __nv_bfloat16 g_B2h[Nn1 * Nn2],  g_B2l[Nn1 * Nn2];

// row-major bf16 A operands: X0 = [h0|p] (ld 256), X1 = [h1|q|h1|r] (ld 512)
__device__ __nv_bfloat16 g_X0qh[Nn0 * 256], g_X0ql[Nn0 * 256];
__device__ __nv_bfloat16 g_X1qh[Nn1 * 512], g_X1ql[Nn1 * 512];

// transposed bf16 buffers
__device__ __nv_bfloat16 g_bt0h[128 * Nn0],  g_bt0l[128 * Nn0];
__device__ __nv_bfloat16 g_bt1ah[128 * Nn1], g_bt1al[128 * Nn1];
__device__ __nv_bfloat16 g_bt2h[128 * Nn2],  g_bt2l[128 * Nn2];
__device__ __nv_bfloat16 g_bb0h[128 * Nn0],  g_bb0l[128 * Nn0];
__device__ __nv_bfloat16 g_bb1ah[128 * Nn1], g_bb1al[128 * Nn1];
__device__ __nv_bfloat16 g_bb1bh[128 * Nn1], g_bb1bl[128 * Nn1];

// combined Horner weights, transposed bf16 hi/lo
#define WSZ (2 * 128 * 128)
__device__ __nv_bfloat16 g_Wn0h[WSZ], g_Wn0l[WSZ];
__device__ __nv_bfloat16 g_Wn1h[WSZ], g_Wn1l[WSZ];
__device__ __nv_bfloat16 g_Wn2h[WSZ], g_Wn2l[WSZ];
__device__ __nv_bfloat16 g_Wm0h[WSZ], g_Wm0l[WSZ];   // layer-1 node weights
__device__ __nv_bfloat16 g_Wm1h[WSZ], g_Wm1l[WSZ];
__device__ __nv_bfloat16 g_Wm2h[WSZ], g_Wm2l[WSZ];
__device__ __nv_bfloat16 g_We0h[WSZ], g_We0l[WSZ];
__device__ __nv_bfloat16 g_WeD1h[WSZ], g_WeD1l[WSZ];
__device__ __nv_bfloat16 g_WeD2h[WSZ], g_WeD2l[WSZ];
__device__ __nv_bfloat16 g_WeU1h[WSZ], g_WeU1l[WSZ];
__device__ __nv_bfloat16 g_WeU2h[WSZ], g_WeU2l[WSZ];
__device__ __nv_bfloat16 g_Werh[128 * 128], g_Werl[128 * 128];

// ================= PTX helpers =================
__device__ __forceinline__ uint32_t smem_u32(const void* p) {
    uint32_t a;
    asm("{ .reg .u64 t; cvta.to.shared.u64 t, %1; cvt.u32.u64 %0, t; }" : "=r"(a) : "l"(p));
    return a;
}
__device__ __forceinline__ void ldsm_x4(uint32_t* r, uint32_t a) {
    asm volatile("ldmatrix.sync.aligned.m8n8.x4.shared.b16 {%0,%1,%2,%3}, [%4];"
                 : "=r"(r[0]), "=r"(r[1]), "=r"(r[2]), "=r"(r[3]) : "r"(a));
}
__device__ __forceinline__ void mma_bf16(float* c, const uint32_t* a, const uint32_t* b) {
    asm volatile(
        "mma.sync.aligned.m16n8k16.row.col.f32.bf16.bf16.f32 "
        "{%0,%1,%2,%3}, {%4,%5,%6,%7}, {%8,%9}, {%0,%1,%2,%3};"
        : "+f"(c[0]), "+f"(c[1]), "+f"(c[2]), "+f"(c[3])
        : "r"(a[0]), "r"(a[1]), "r"(a[2]), "r"(a[3]), "r"(b[0]), "r"(b[1]));
}
__device__ __forceinline__ void cp_async16(uint32_t dst, const void* src, int sz) {
    asm volatile("cp.async.cg.shared.global [%0], [%1], 16, %2;"
                 :: "r"(dst), "l"(src), "r"(sz));
}
__device__ __forceinline__ uint32_t sw_addr(uint32_t tile_base, int r, int chunk) {
    return tile_base + (uint32_t)(r * 64) + (uint32_t)((chunk ^ ((r >> 1) & 3)) << 4);
}

// ================= batched bf16x3 HMMA GEMM + fused epilogue =================
#define MM_SMEM (3 * 4 * 8192)
#define MAXJOB 14

struct MMJob {
    const __nv_bfloat16 *Ah, *Al, *Bh, *Bl;
    float* Cf;
    __nv_bfloat16 *Rh, *Rl;
    __nv_bfloat16 *Th, *Tl;
    int M, K, lda, ldb, ldc, ldR, ldT, tileStart, tilesX;
};
struct MMParams { MMJob j[MAXJOB]; int n; };

__global__ __launch_bounds__(256, 2)
void mmb_kernel(MMParams P)
{
    extern __shared__ __align__(128) char smem[];
    const uint32_t sbase = smem_u32(smem);
    const int tid = threadIdx.x, lane = tid & 31, wid = tid >> 5;
    const int wm = wid & 1, wn = wid >> 1;

    int bt = blockIdx.x;
    int ji = 0;
#pragma unroll 1
    while (ji + 1 < P.n && bt >= P.j[ji + 1].tileStart) ji++;
    const MMJob jb = P.j[ji];
    const int rel = bt - jb.tileStart;
    const int m0 = (rel % jb.tilesX) * 128;
    const int n0 = (rel / jb.tilesX) * 128;
    const int M = jb.M, K = jb.K, lda = jb.lda, ldb = jb.ldb;
    const int mrows = (M - m0 < 128) ? (M - m0) : 128;
    const __nv_bfloat16* Ah = jb.Ah + (size_t)m0 * lda;
    const __nv_bfloat16* Al = jb.Al + (size_t)m0 * lda;
    const __nv_bfloat16* Bh = jb.Bh + (size_t)n0 * ldb;
    const __nv_bfloat16* Bl = jb.Bl + (size_t)n0 * ldb;
    const int nk = (K + 31) >> 5;

    float acc[4][4][4];
#pragma unroll
    for (int i = 0; i < 4; i++)
#pragma unroll
        for (int j = 0; j < 4; j++)
#pragma unroll
            for (int v = 0; v < 4; v++) acc[i][j][v] = 0.f;

    auto load_stage = [&](int t) {
        const uint32_t sb = sbase + (uint32_t)(t % 3) * 32768;
        const int k0 = t << 5;
#pragma unroll
        for (int i = 0; i < 8; i++) {
            int idx = tid + i * 256;
            int tile = idx >> 9;
            int rem  = idx & 511;
            int r = rem >> 2, c = rem & 3;
            const __nv_bfloat16* gp;
            int ok;
            if (tile < 2) {
                gp = (tile == 0 ? Ah : Al) + (size_t)r * lda + k0 + c * 8;
                ok = (r < mrows) && (k0 + c * 8 < K);
            } else {
                gp = (tile == 2 ? Bh : Bl) + (size_t)r * ldb + k0 + c * 8;
                ok = (k0 + c * 8 < K);
            }
            cp_async16(sb + (uint32_t)tile * 8192 + sw_addr(0, r, c), gp, ok ? 16 : 0);
        }
    };

#pragma unroll
    for (int s = 0; s < 2; s++) {
        if (s < nk) load_stage(s);
        asm volatile("cp.async.commit_group;" ::: "memory");
    }

    const int frag_r = lane & 15;
    const int frag_c = lane >> 4;

    for (int t = 0; t < nk; t++) {
        asm volatile("cp.async.wait_group 1;" ::: "memory");
        __syncthreads();
        const uint32_t sb = sbase + (uint32_t)(t % 3) * 32768;
        const uint32_t tAh = sb, tAl = sb + 8192, tBh = sb + 16384, tBl = sb + 24576;

#pragma unroll
        for (int ks = 0; ks < 2; ks++) {
            const int ch = ks * 2 + frag_c;
            uint32_t bh[4][2], bl[4][2];
#pragma unroll
            for (int j = 0; j < 2; j++) {
                int r = wn * 32 + j * 16 + frag_r;
                uint32_t rr[4];
                ldsm_x4(rr, sw_addr(tBh, r, ch));
                bh[2 * j][0] = rr[0]; bh[2 * j][1] = rr[2];
                bh[2 * j + 1][0] = rr[1]; bh[2 * j + 1][1] = rr[3];
                ldsm_x4(rr, sw_addr(tBl, r, ch));
                bl[2 * j][0] = rr[0]; bl[2 * j][1] = rr[2];
                bl[2 * j + 1][0] = rr[1]; bl[2 * j + 1][1] = rr[3];
            }
#pragma unroll
            for (int mt = 0; mt < 4; mt++) {
                int r = wm * 64 + mt * 16 + frag_r;
                uint32_t ah[4], al[4];
                ldsm_x4(ah, sw_addr(tAh, r, ch));
                ldsm_x4(al, sw_addr(tAl, r, ch));
#pragma unroll
                for (int nt = 0; nt < 4; nt++) mma_bf16(acc[mt][nt], ah, bh[nt]);
#pragma unroll
                for (int nt = 0; nt < 4; nt++) mma_bf16(acc[mt][nt], ah, bl[nt]);
#pragma unroll
                for (int nt = 0; nt < 4; nt++) mma_bf16(acc[mt][nt], al, bh[nt]);
            }
        }
        if (t + 2 < nk) load_stage(t + 2);
        asm volatile("cp.async.commit_group;" ::: "memory");
    }

    // ---- fused epilogue: fp32 / row-bf16 / transposed-bf16 ----
    const int er = lane >> 2, ec = (lane & 3) * 2;
    const bool doBF = (jb.Rh != nullptr) || (jb.Th != nullptr);
#pragma unroll
    for (int mt = 0; mt < 4; mt++) {
        int r0 = m0 + wm * 64 + mt * 16 + er;
        int r1 = r0 + 8;
#pragma unroll
        for (int nt = 0; nt < 4; nt++) {
            int col = n0 + wn * 32 + nt * 8 + ec;
            float f0 = acc[mt][nt][0], f1 = acc[mt][nt][1];
            float f2 = acc[mt][nt][2], f3 = acc[mt][nt][3];
            if (jb.Cf) {
                if (r0 < M) *(float2*)&jb.Cf[(size_t)r0 * jb.ldc + col] = make_float2(f0, f1);
                if (r1 < M) *(float2*)&jb.Cf[(size_t)r1 * jb.ldc + col] = make_float2(f2, f3);
            }
            if (doBF) {
                __nv_bfloat16 h0 = __float2bfloat16(f0), h1 = __float2bfloat16(f1);
                __nv_bfloat16 h2 = __float2bfloat16(f2), h3 = __float2bfloat16(f3);
                __nv_bfloat16 l0 = __float2bfloat16(f0 - __bfloat162float(h0));
                __nv_bfloat16 l1 = __float2bfloat16(f1 - __bfloat162float(h1));
                __nv_bfloat16 l2 = __float2bfloat16(f2 - __bfloat162float(h2));
                __nv_bfloat16 l3 = __float2bfloat16(f3 - __bfloat162float(h3));
                if (jb.Rh) {
                    if (r0 < M) {
                        *(__nv_bfloat162*)&jb.Rh[(size_t)r0 * jb.ldR + col] = __halves2bfloat162(h0, h1);
                        *(__nv_bfloat162*)&jb.Rl[(size_t)r0 * jb.ldR + col] = __halves2bfloat162(l0, l1);
                    }
                    if (r1 < M) {
                        *(__nv_bfloat162*)&jb.Rh[(size_t)r1 * jb.ldR + col] = __halves2bfloat162(h2, h3);
                        *(__nv_bfloat162*)&jb.Rl[(size_t)r1 * jb.ldR + col] = __halves2bfloat162(l2, l3);
                    }
                }
                if (jb.Th) {
                    size_t cA = (size_t)col * jb.ldT, cB = (size_t)(col + 1) * jb.ldT;
                    if (r0 < M) {
                        jb.Th[cA + r0] = h0; jb.Th[cB + r0] = h1;
                        jb.Tl[cA + r0] = l0; jb.Tl[cB + r0] = l1;
                    }
                    if (r1 < M) {
                        jb.Th[cA + r1] = h2; jb.Th[cB + r1] = h3;
                        jb.Tl[cA + r1] = l2; jb.Tl[cB + r1] = l3;
                    }
                }
            }
        }
    }
}

// ================= reduce-convert =================
struct RJob {
    const float* base; int nP, pStride, M, N;
    __nv_bfloat16 *Rh, *Rl; int ldR;
    __nv_bfloat16 *Th, *Tl; int ldT;
    float* Cf; int ldc;
    int tileStart, tilesR;
};
struct RParams { RJob j[4]; int n; };

__global__ void rcvt_kernel(RParams P)
{
    __shared__ float tile[32][33];
    int b = blockIdx.x;
    int ji = 0;
#pragma unroll 1
    while (ji + 1 < P.n && b >= P.j[ji + 1].tileStart) ji++;
    const RJob jb = P.j[ji];
    int rel = b - jb.tileStart;
    int r0 = (rel % jb.tilesR) * 32, c0 = (rel / jb.tilesR) * 32;
    int tx = threadIdx.x, ty = threadIdx.y;
    for (int i = ty; i < 32; i += 8) {
        int r = r0 + i, c = c0 + tx;
        float v = 0.f;
        if (r < jb.M) {
            size_t off = (size_t)r * jb.N + c;
#pragma unroll 1
            for (int s = 0; s < jb.nP; s++) v += jb.base[off + (size_t)s * jb.pStride];
        }
        tile[i][tx] = v;
        if (r < jb.M) {
            if (jb.Cf) jb.Cf[(size_t)r * jb.ldc + c] = v;
            if (jb.Rh) {
                __nv_bfloat16 h = __float2bfloat16(v);
                jb.Rh[(size_t)r * jb.ldR + c] = h;
                jb.Rl[(size_t)r * jb.ldR + c] = __float2bfloat16(v - __bfloat162float(h));
            }
        }
    }
    __syncthreads();
    if (!jb.Th) return;
    for (int i = ty; i < 32; i += 8) {
        int c = c0 + i, r = r0 + tx;
        if (r < jb.M) {
            float v = tile[tx][i];
            __nv_bfloat16 h = __float2bfloat16(v);
            size_t idx = (size_t)c * jb.ldT + r;
            jb.Th[idx] = h;
            jb.Tl[idx] = __float2bfloat16(v - __bfloat162float(h));
        }
    }
}

// ================= operator split =================
struct SJob { const float* src; __nv_bfloat16 *dh, *dl; int n8, blkStart; };
struct SParams { SJob j[8]; int n; };

__global__ void splitb_kernel(SParams P)
{
    int b = blockIdx.x;
    int ji = 0;
#pragma unroll 1
    while (ji + 1 < P.n && b >= P.j[ji + 1].blkStart) ji++;
    const SJob jb = P.j[ji];
    int i = (b - jb.blkStart) * 256 + threadIdx.x;
    if (i >= jb.n8) return;
    float4 v0 = ((const float4*)jb.src)[i * 2];
    float4 v1 = ((const float4*)jb.src)[i * 2 + 1];
    __nv_bfloat162 h[4], l[4];
    h[0] = __floats2bfloat162_rn(v0.x, v0.y);
    h[1] = __floats2bfloat162_rn(v0.z, v0.w);
    h[2] = __floats2bfloat162_rn(v1.x, v1.y);
    h[3] = __floats2bfloat162_rn(v1.z, v1.w);
    l[0] = __floats2bfloat162_rn(v0.x - __bfloat162float(h[0].x), v0.y - __bfloat162float(h[0].y));
    l[1] = __floats2bfloat162_rn(v0.z - __bfloat162float(h[1].x), v0.w - __bfloat162float(h[1].y));
    l[2] = __floats2bfloat162_rn(v1.x - __bfloat162float(h[2].x), v1.y - __bfloat162float(h[2].y));
    l[3] = __floats2bfloat162_rn(v1.z - __bfloat162float(h[3].x), v1.w - __bfloat162float(h[3].y));
    ((uint4*)jb.dh)[i] = *(uint4*)h;
    ((uint4*)jb.dl)[i] = *(uint4*)l;
}

// ================= transpose-split (B1^T) =================
__global__ void tsplit1_kernel(const float* __restrict__ src,
                               __nv_bfloat16* __restrict__ dh, __nv_bfloat16* __restrict__ dl,
                               int lds, int rows, int cols, int tilesR)
{
    __shared__ float tile[32][33];
    int rel = blockIdx.x;
    int k0 = (rel % tilesR) * 32, n0 = (rel / tilesR) * 32;
    int tx = threadIdx.x, ty = threadIdx.y;
    for (int i = ty; i < 32; i += 8) {
        int k = k0 + i, n = n0 + tx;
        tile[i][tx] = (k < rows && n < cols) ? src[(size_t)k * lds + n] : 0.f;
    }
    __syncthreads();
    for (int i = ty; i < 32; i += 8) {
        int n = n0 + i, k = k0 + tx;
        if (n < cols && k < rows) {
            float v = tile[tx][i];
            __nv_bfloat16 h = __float2bfloat16(v);
            dh[(size_t)n * rows + k] = h;
            dl[(size_t)n * rows + k] = __float2bfloat16(v - __bfloat162float(h));
        }
    }
}

// ================= hconv =================
struct HJob {
    const float* src;
    __nv_bfloat16 *Rh, *Rl, *R2h, *R2l;
    __nv_bfloat16 *Th, *Tl;
    int rows, ldR, tileStart, tilesR;
};
struct HParams { HJob j[3]; int n; };

__global__ void hconv_kernel(HParams P)
{
    __shared__ float tile[32][33];
    int b = blockIdx.x;
    int ji = 0;
#pragma unroll 1
    while (ji + 1 < P.n && b >= P.j[ji + 1].tileStart) ji++;
    const HJob jb = P.j[ji];
    int rel = b - jb.tileStart;
    int r0 = (rel % jb.tilesR) * 32, c0 = (rel / jb.tilesR) * 32;
    int tx = threadIdx.x, ty = threadIdx.y;
    for (int i = ty; i < 32; i += 8) {
        int r = r0 + i, c = c0 + tx;
        float v = (r < jb.rows) ? jb.src[(size_t)r * CC + c] : 0.f;
        tile[i][tx] = v;
        if (r < jb.rows && jb.Rh) {
            __nv_bfloat16 h = __float2bfloat16(v);
            __nv_bfloat16 l = __float2bfloat16(v - __bfloat162float(h));
            jb.Rh[(size_t)r * jb.ldR + c] = h;
            jb.Rl[(size_t)r * jb.ldR + c] = l;
            if (jb.R2h) { jb.R2h[(size_t)r * jb.ldR + c] = h; jb.R2l[(size_t)r * jb.ldR + c] = l; }
        }
    }
    __syncthreads();
    if (!jb.Th) return;
    for (int i = ty; i < 32; i += 8) {
        int c = c0 + i, r = r0 + tx;
        if (r < jb.rows) {
            float v = tile[tx][i];
            __nv_bfloat16 h = __float2bfloat16(v);
            size_t idx = (size_t)c * jb.rows + r;
            jb.Th[idx] = h;
            jb.Tl[idx] = __float2bfloat16(v - __bfloat162float(h));
        }
    }
}

// ================= input linear =================
struct LJob { const float *x, *W, *b; float* y; int rows, rowStart; };
struct LParams { LJob j[3]; int n; };

__global__ void linb_kernel(LParams P)
{
    __shared__ float xs[CC];
    int b = blockIdx.x;
    int ji = 0;
#pragma unroll 1
    while (ji + 1 < P.n && b >= P.j[ji + 1].rowStart) ji++;
    const LJob jb = P.j[ji];
    int n = b - jb.rowStart, o = threadIdx.x;
    xs[o] = jb.x[(size_t)n * CC + o];
    __syncthreads();
    float acc = jb.b[o];
    const float* wr = &jb.W[(size_t)o * CC];
#pragma unroll 8
    for (int i = 0; i < CC; i++) acc += xs[i] * wr[i];
    jb.y[(size_t)n * CC + o] = acc;
}

// ================= Horner weight builder =================
struct WJob { const float* w; __nv_bfloat16 *dh, *dl; int korig, m0, m1, blkStart; };
struct WParams { WJob j[12]; int n; };

__global__ void wbuild_kernel(WParams P)
{
    int b = blockIdx.x;
    int ji = 0;
#pragma unroll 1
    while (ji + 1 < P.n && b >= P.j[ji + 1].blkStart) ji++;
    const WJob jb = P.j[ji];
    int rel = b - jb.blkStart;
    int s = rel >> 7, o = rel & 127;
    int i = threadIdx.x;
    int S = (jb.m1 == -2) ? 1 : 2;
    int k = (s == 0) ? jb.m0 : jb.m1;
    float v = (k >= 0) ? jb.w[((size_t)i * CC + o) * jb.korig + k] : 0.f;
    __nv_bfloat16 h = __float2bfloat16(v);
    size_t idx = (size_t)o * (S * 128) + s * 128 + i;
    jb.dh[idx] = h;
    jb.dl[idx] = __float2bfloat16(v - __bfloat162float(h));
}

__global__ void head_kernel(const float* __restrict__ h0, const float* __restrict__ ow,
                            const float* __restrict__ ob, float* __restrict__ out, int total)
{
    int idx = blockIdx.x * blockDim.x + threadIdx.x;
    if (idx >= total) return;
    int n = idx >> 1, c = idx & 1;
    float acc = ob[c];
    const float* hr = &h0[(size_t)n * CC];
    const float* wr = &ow[(size_t)c * CC];
#pragma unroll 8
    for (int i = 0; i < CC; i++) acc += hr[i] * wr[i];
    out[idx] = 1.f / (1.f + expf(-acc));
}

// ================= host-side builders =================
struct MMBatch { MMParams p; int tiles; };
static void mmAdd(MMBatch& b,
                  const __nv_bfloat16* Ah, const __nv_bfloat16* Al, int lda,
                  const __nv_bfloat16* Bh, const __nv_bfloat16* Bl, int ldb,
                  int M, int N, int K,
                  float* Cf, int ldc,
                  __nv_bfloat16* Rh = nullptr, __nv_bfloat16* Rl = nullptr, int ldR = 0,
                  __nv_bfloat16* Th = nullptr, __nv_bfloat16* Tl = nullptr, int ldT = 0)
{
    MMJob& j = b.p.j[b.p.n++];
    j.Ah = Ah; j.Al = Al; j.Bh = Bh; j.Bl = Bl;
    j.Cf = Cf; j.Rh = Rh; j.Rl = Rl; j.Th = Th; j.Tl = Tl;
    j.M = M; j.K = K; j.lda = lda; j.ldb = ldb; j.ldc = ldc; j.ldR = ldR; j.ldT = ldT;
    j.tileStart = b.tiles; j.tilesX = (M + 127) / 128;
    b.tiles += j.tilesX * (N / 128);
}
static void mmAddSplit(MMBatch& b,
                       const __nv_bfloat16* Ah, const __nv_bfloat16* Al, int lda,
                       const __nv_bfloat16* Bh, const __nv_bfloat16* Bl, int ldb,
                       int M, int N, int K, int nsp, float* part)
{
    int chunk = (((K + nsp - 1) / nsp) + 7) & ~7;
    for (int s = 0; s < nsp; s++) {
        int k0 = s * chunk;
        int kl = (K - k0 < chunk) ? (K - k0) : chunk;
        mmAdd(b, Ah + k0, Al + k0, lda, Bh + k0, Bl + k0, ldb, M, N, kl,
              part + (size_t)s * M * N, N);
    }
}
static void mmRun(MMBatch& b)
{
    if (b.p.n) mmb_kernel<<<b.tiles, 256, MM_SMEM>>>(b.p);
    b.p.n = 0; b.tiles = 0;
}

struct RBatch { RParams p; int tiles; };
static void rAdd(RBatch& b, const float* base, int nP, int M, int N,
                 __nv_bfloat16* Rh, __nv_bfloat16* Rl, int ldR,
                 __nv_bfloat16* Th, __nv_bfloat16* Tl, int ldT,
                 float* Cf = nullptr, int ldc = 0)
{
    RJob& j = b.p.j[b.p.n++];
    j.base = base; j.nP = nP; j.pStride = M * N; j.M = M; j.N = N;
    j.Rh = Rh; j.Rl = Rl; j.ldR = ldR; j.Th = Th; j.Tl = Tl; j.ldT = ldT;
    j.Cf = Cf; j.ldc = ldc;
    j.tileStart = b.tiles; j.tilesR = (M + 31) / 32;
    b.tiles += j.tilesR * (N / 32);
}
static void rRun(RBatch& b)
{
    if (b.p.n) rcvt_kernel<<<b.tiles, dim3(32, 8)>>>(b.p);
    b.p.n = 0; b.tiles = 0;
}

#define SYM(v, g) { void* p_; cudaGetSymbolAddress(&p_, g); v = (decltype(v))p_; }

extern "C" void kernel_launch(void* const* d_in, const int* in_sizes, int n_in,
                              void* d_out, int out_size)
{
    (void)in_sizes; (void)n_in; (void)out_size;
    const float* x0    = (const float*)d_in[0];
    const float* x1    = (const float*)d_in[1];
    const float* x2    = (const float*)d_in[2];
    const float* L0    = (const float*)d_in[3];
    const float* L1d   = (const float*)d_in[4];
    const float* L1u   = (const float*)d_in[5];
    const float* B1    = (const float*)d_in[8];
    const float* B2    = (const float*)d_in[9];
    const float* in_w0 = (const float*)d_in[10];
    const float* in_b0 = (const float*)d_in[11];
    const float* in_w1 = (const float*)d_in[12];
    const float* in_b1 = (const float*)d_in[13];
    const float* in_w2 = (const float*)d_in[14];
    const float* in_b2 = (const float*)d_in[15];
    const float* l0_w0 = (const float*)d_in[16];
    const float* l0_w1 = (const float*)d_in[17];
    const float* l1_w0 = (const float*)d_in[19];
    const float* out_w = (const float*)d_in[22];
    const float* out_b = (const float*)d_in[23];
    float* out = (float*)d_out;

    cudaFuncSetAttribute(mmb_kernel, cudaFuncAttributeMaxDynamicSharedMemorySize, MM_SMEM);

    float *h0, *h1, *h2, *pool;
    SYM(h0, g_h0); SYM(h1, g_h1); SYM(h2, g_h2); SYM(pool, g_part);
    __nv_bfloat16 *L0h, *L0l, *L1dh, *L1dl, *L1uh, *L1ul;
    __nv_bfloat16 *B1h, *B1l, *B1th, *B1tl, *B2h, *B2l;
    SYM(L0h, g_L0h); SYM(L0l, g_L0l);
    SYM(L1dh, g_L1dh); SYM(L1dl, g_L1dl); SYM(L1uh, g_L1uh); SYM(L1ul, g_L1ul);
    SYM(B1h, g_B1h); SYM(B1l, g_B1l); SYM(B1th, g_B1th); SYM(B1tl, g_B1tl);
    SYM(B2h, g_B2h); SYM(B2l, g_B2l);
    __nv_bfloat16 *X0qh, *X0ql, *X1qh, *X1ql;
    SYM(X0qh, g_X0qh); SYM(X0ql, g_X0ql); SYM(X1qh, g_X1qh); SYM(X1ql, g_X1ql);
    __nv_bfloat16 *bt0h, *bt0l, *bt1ah, *bt1al, *bt2h, *bt2l;
    SYM(bt0h, g_bt0h); SYM(bt0l, g_bt0l);
    SYM(bt1ah, g_bt1ah); SYM(bt1al, g_bt1al);
    SYM(bt2h, g_bt2h); SYM(bt2l, g_bt2l);
    __nv_bfloat16 *bb0h, *bb0l, *bb1ah, *bb1al, *bb1bh, *bb1bl;
    SYM(bb0h, g_bb0h); SYM(bb0l, g_bb0l);
    SYM(bb1ah, g_bb1ah); SYM(bb1al, g_bb1al);
    SYM(bb1bh, g_bb1bh); SYM(bb1bl, g_bb1bl);
    __nv_bfloat16 *Wn0h, *Wn0l, *Wn1h, *Wn1l, *Wn2h, *Wn2l;
    __nv_bfloat16 *Wm0h, *Wm0l, *Wm1h, *Wm1l, *Wm2h, *Wm2l;
    __nv_bfloat16 *We0h, *We0l, *WeD1h, *WeD1l, *WeD2h, *WeD2l;
    __nv_bfloat16 *WeU1h, *WeU1l, *WeU2h, *WeU2l, *Werh, *Werl;
    SYM(Wn0h, g_Wn0h); SYM(Wn0l, g_Wn0l);
    SYM(Wn1h, g_Wn1h); SYM(Wn1l, g_Wn1l);
    SYM(Wn2h, g_Wn2h); SYM(Wn2l, g_Wn2l);
    SYM(Wm0h, g_Wm0h); SYM(Wm0l, g_Wm0l);
    SYM(Wm1h, g_Wm1h); SYM(Wm1l, g_Wm1l);
    SYM(Wm2h, g_Wm2h); SYM(Wm2l, g_Wm2l);
    SYM(We0h, g_We0h); SYM(We0l, g_We0l);
    SYM(WeD1h, g_WeD1h); SYM(WeD1l, g_WeD1l);
    SYM(WeD2h, g_WeD2h); SYM(WeD2l, g_WeD2l);
    SYM(WeU1h, g_WeU1h); SYM(WeU1l, g_WeU1l);
    SYM(WeU2h, g_WeU2h); SYM(WeU2l, g_WeU2l);
    SYM(Werh, g_Werh); SYM(Werl, g_Werl);

    const size_t SZ0 = (size_t)Nn0 * 128, SZ1 = (size_t)Nn1 * 128;
    // pool layout (floats). Phase A (projections): Pp/Pq/Pr. Freed after P2 rcvt.
    const size_t OFF_Pp = 0;           // 4*SZ0 = 1.02M
    const size_t OFF_Pq = 1100000;     // 2*SZ1 = 1.54M
    const size_t OFF_Pr = 2700000;     // 3*SZ1 = 2.30M
    // Phase B: H1 (12 slots: D0-4,U5-9,We0=10,Wer=11), H0 (5: L0 0-3, base 4)
    const size_t OFF_H1 = 0;           // 12*SZ1 = 9.22M
    const size_t OFF_H0 = 9300000;     // 5*SZ0 = 1.28M
    // Phase B: P6 pools PD/PU (6 slots: splits 0-4, u 5), PN (5: splits 0-3, u 4)
    const size_t OFF_PD = 10600000;    // 6*SZ1 = 4.61M
    const size_t OFF_PU = 15300000;    // 6*SZ1
    const size_t OFF_PN = 20000000;    // 5*SZ0 = 1.28M
    // Phase C (layer 1): all within freed regions
    const size_t OFF_L1P = 0;          // 6*SZ0
    const size_t OFF_R1 = 2000000;     // 5*SZ0
    const size_t OFF_R2 = 3500000;     // 5*SZ0

    MMBatch mb = {}; RBatch rb = {};

    // ---- operator splits ----
    {
        SParams sp = {};
        int blks = 0;
        auto add = [&](const float* s, __nv_bfloat16* dh, __nv_bfloat16* dl, size_t cnt) {
            SJob& j = sp.j[sp.n++];
            j.src = s; j.dh = dh; j.dl = dl; j.n8 = (int)(cnt / 8); j.blkStart = blks;
            blks += (j.n8 + 255) / 256;
        };
        add(L1d, L1dh, L1dl, (size_t)Nn1 * Nn1);
        add(L1u, L1uh, L1ul, (size_t)Nn1 * Nn1);
        add(B1,  B1h,  B1l,  (size_t)Nn0 * Nn1);
        add(B2,  B2h,  B2l,  (size_t)Nn1 * Nn2);
        add(L0,  L0h,  L0l,  (size_t)Nn0 * Nn0);
        splitb_kernel<<<blks, 256>>>(sp);
    }
    tsplit1_kernel<<<((Nn0 + 31) / 32) * ((Nn1 + 31) / 32), dim3(32, 8)>>>(
        B1, B1th, B1tl, Nn1, Nn0, Nn1, (Nn0 + 31) / 32);

    // ---- input linears ----
    {
        LParams lp = {};
        lp.j[0] = { x0, in_w0, in_b0, h0, Nn0, 0 };
        lp.j[1] = { x1, in_w1, in_b1, h1, Nn1, Nn0 };
        lp.j[2] = { x2, in_w2, in_b2, h2, Nn2, Nn0 + Nn1 };
        lp.n = 3;
        linb_kernel<<<Nn0 + Nn1 + Nn2, CC>>>(lp);
    }

    // ---- ALL Horner weights (both layers, one launch) ----
    {
        WParams wp = {};
        int blk = 0;
        auto add = [&](const float* w, __nv_bfloat16* dh, __nv_bfloat16* dl,
                       int korig, int m0, int m1) {
            WJob& j = wp.j[wp.n++];
            j.w = w; j.dh = dh; j.dl = dl; j.korig = korig; j.m0 = m0; j.m1 = m1;
            j.blkStart = blk;
            blk += ((m1 == -2) ? 1 : 2) * 128;
        };
        add(l0_w0, Wn0h, Wn0l, 6, 0, 3);
        add(l0_w0, Wn1h, Wn1l, 6, 1, 4);
        add(l0_w0, Wn2h, Wn2l, 6, 2, 5);
        add(l0_w1, We0h, We0l, 11, 0, 5);
        add(l0_w1, WeD1h, WeD1l, 11, 1, 6);
        add(l0_w1, WeD2h, WeD2l, 11, 2, 7);
        add(l0_w1, WeU1h, WeU1l, 11, 3, 9);
        add(l0_w1, WeU2h, WeU2l, 11, 4, 10);
        add(l0_w1, Werh, Werl, 11, 8, -2);
        add(l1_w0, Wm0h, Wm0l, 6, 0, 3);
        add(l1_w0, Wm1h, Wm1l, 6, 1, 4);
        add(l1_w0, Wm2h, Wm2l, 6, 2, 5);
        wbuild_kernel<<<blk, 128>>>(wp);
    }

    // ---- hconv ----
    {
        HParams hp = {};
        int tiles = 0;
        int tr0 = (Nn0 + 31) / 32, tr1 = (Nn1 + 31) / 32, tr2 = (Nn2 + 31) / 32;
        hp.j[0] = { h0, X0qh, X0ql, nullptr, nullptr, bt0h, bt0l, Nn0, 256, tiles, tr0 };
        tiles += tr0 * 4;
        hp.j[1] = { h1, X1qh, X1ql, X1qh + 256, X1ql + 256, bt1ah, bt1al, Nn1, 512, tiles, tr1 };
        tiles += tr1 * 4;
        hp.j[2] = { h2, nullptr, nullptr, nullptr, nullptr, bt2h, bt2l, Nn2, 0, tiles, tr2 };
        tiles += tr2 * 4;
        hp.n = 3;
        hconv_kernel<<<tiles, dim3(32, 8)>>>(hp);
    }

    // P2: projections (299 CTAs ~ 1 wave)
    mmAddSplit(mb, B1h,  B1l,  Nn1, bt1ah, bt1al, Nn1, Nn0, 128, Nn1, 4, pool + OFF_Pp);
    mmAddSplit(mb, B2h,  B2l,  Nn2, bt2h,  bt2l,  Nn2, Nn1, 128, Nn2, 3, pool + OFF_Pr);
    mmAddSplit(mb, B1th, B1tl, Nn0, bt0h,  bt0l,  Nn0, Nn1, 128, Nn0, 2, pool + OFF_Pq);
    mmRun(mb);
    rAdd(rb, pool + OFF_Pp, 4, Nn0, 128, X0qh + 128, X0ql + 128, 256, nullptr, nullptr, 0);
    rAdd(rb, pool + OFF_Pr, 3, Nn1, 128, X1qh + 384, X1ql + 384, 512, nullptr, nullptr, 0);
    rAdd(rb, pool + OFF_Pq, 2, Nn1, 128, X1qh + 128, X1ql + 128, 512, nullptr, nullptr, 0);
    rRun(rb);

    // P4: ALL channel mixes. Inner -> T-epilogue; u-terms/bases -> pool slots.
    mmAdd(mb, X1qh, X1ql, 512, WeD2h, WeD2l, 256, Nn1, 128, 256,
          nullptr, 0, nullptr, nullptr, 0, bb1ah, bb1al, Nn1);
    mmAdd(mb, X1qh + 256, X1ql + 256, 512, WeU2h, WeU2l, 256, Nn1, 128, 256,
          nullptr, 0, nullptr, nullptr, 0, bb1bh, bb1bl, Nn1);
    mmAdd(mb, X0qh, X0ql, 256, Wn2h, Wn2l, 256, Nn0, 128, 256,
          nullptr, 0, nullptr, nullptr, 0, bb0h, bb0l, Nn0);
    mmAdd(mb, X1qh, X1ql, 512, WeD1h, WeD1l, 256, Nn1, 128, 256, pool + OFF_PD + 5 * SZ1, 128);
    mmAdd(mb, X1qh + 256, X1ql + 256, 512, WeU1h, WeU1l, 256, Nn1, 128, 256, pool + OFF_PU + 5 * SZ1, 128);
    mmAdd(mb, X0qh, X0ql, 256, Wn1h, Wn1l, 256, Nn0, 128, 256, pool + OFF_PN + 4 * SZ0, 128);
    mmAdd(mb, X1qh, X1ql, 512, We0h, We0l, 256, Nn1, 128, 256, pool + OFF_H1 + 10 * SZ1, 128);
    mmAdd(mb, X1qh + 384, X1ql + 384, 512, Werh, Werl, 128, Nn1, 128, 128, pool + OFF_H1 + 11 * SZ1, 128);
    mmAdd(mb, X0qh, X0ql, 256, Wn0h, Wn0l, 256, Nn0, 128, 256, pool + OFF_H0 + 4 * SZ0, 128);
    mmRun(mb);

    // P6: first Horner hops (534 CTAs = 2 waves @ K<=1200)
    mmAddSplit(mb, L1dh, L1dl, Nn1, bb1ah, bb1al, Nn1, Nn1, 128, Nn1, 5, pool + OFF_PD);
    mmAddSplit(mb, L1uh, L1ul, Nn1, bb1bh, bb1bl, Nn1, Nn1, 128, Nn1, 5, pool + OFF_PU);
    mmAddSplit(mb, L0h,  L0l,  Nn0, bb0h,  bb0l,  Nn0, Nn0, 128, Nn0, 4, pool + OFF_PN);
    mmRun(mb);
    rAdd(rb, pool + OFF_PD, 6, Nn1, 128, nullptr, nullptr, 0, bb1ah, bb1al, Nn1);
    rAdd(rb, pool + OFF_PU, 6, Nn1, 128, nullptr, nullptr, 0, bb1bh, bb1bl, Nn1);
    rAdd(rb, pool + OFF_PN, 5, Nn0, 128, nullptr, nullptr, 0, bb0h, bb0l, Nn0);
    rRun(rb);

    // P8: second Horner hops
    mmAddSplit(mb, L1dh, L1dl, Nn1, bb1ah, bb1al, Nn1, Nn1, 128, Nn1, 5, pool + OFF_H1);
    mmAddSplit(mb, L1uh, L1ul, Nn1, bb1bh, bb1bl, Nn1, Nn1, 128, Nn1, 5, pool + OFF_H1 + 5 * SZ1);
    mmAddSplit(mb, L0h,  L0l,  Nn0, bb0h,  bb0l,  Nn0, Nn0, 128, Nn0, 4, pool + OFF_H0);
    mmRun(mb);

    // h1' (transposed) and h0' (row)
    rAdd(rb, pool + OFF_H1, 12, Nn1, 128, nullptr, nullptr, 0, bt1ah, bt1al, Nn1);
    rAdd(rb, pool + OFF_H0, 5, Nn0, 128, X0qh, X0ql, 256, nullptr, nullptr, 0);
    rRun(rb);

    // ============ LAYER 1 ============
    // p' = B1 @ h1'
    mmAddSplit(mb, B1h, B1l, Nn1, bt1ah, bt1al, Nn1, Nn0, 128, Nn1, 6, pool + OFF_L1P);
    mmRun(mb);
    rAdd(rb, pool + OFF_L1P, 6, Nn0, 128, X0qh + 128, X0ql + 128, 256, nullptr, nullptr, 0);
    rRun(rb);

    // inner (T-epi) + u-term + base in one launch
    mmAdd(mb, X0qh, X0ql, 256, Wm2h, Wm2l, 256, Nn0, 128, 256,
          nullptr, 0, nullptr, nullptr, 0, bb0h, bb0l, Nn0);
    mmAdd(mb, X0qh, X0ql, 256, Wm1h, Wm1l, 256, Nn0, 128, 256, pool + OFF_R1 + 4 * SZ0, 128);
    mmAdd(mb, X0qh, X0ql, 256, Wm0h, Wm0l, 256, Nn0, 128, 256, pool + OFF_R2 + 4 * SZ0, 128);
    mmRun(mb);

    // hop1 + u
    mmAddSplit(mb, L0h, L0l, Nn0, bb0h, bb0l, Nn0, Nn0, 128, Nn0, 4, pool + OFF_R1);
    mmRun(mb);
    rAdd(rb, pool + OFF_R1, 5, Nn0, 128, nullptr, nullptr, 0, bb0h, bb0l, Nn0);
    rRun(rb);

    // hop2 + base -> fp32 h0''
    mmAddSplit(mb, L0h, L0l, Nn0, bb0h, bb0l, Nn0, Nn0, 128, Nn0, 4, pool + OFF_R2);
    mmRun(mb);
    rAdd(rb, pool + OFF_R2, 5, Nn0, 128, nullptr, nullptr, 0, nullptr, nullptr, 0, h0, 128);
    rRun(rb);

    head_kernel<<<(Nn0 * 2 + 255) / 256, 256>>>(h0, out_w, out_b, out, Nn0 * 2);
}

// round 15
// speedup vs baseline: 1.0273x; 1.0273x over previous
#include <cuda_runtime.h>
#include <cuda_bf16.h>
#include <math.h>
#include <stdint.h>

#define Nn0 2000
#define Nn1 6000
#define Nn2 4000
#define CC  128

// ================= static scratch (no allocation) =================
__device__ float g_h0[Nn0 * CC];
__device__ float g_h1[Nn1 * CC];
__device__ float g_h2[Nn2 * CC];

__device__ float g_part[24 * 1024 * 1024];   // fp32 partial pool (96MB)

// operators bf16 hi/lo
__device__ __nv_bfloat16 g_L0h[Nn0 * Nn0],  g_L0l[Nn0 * Nn0];
__device__ __nv_bfloat16 g_L1dh[Nn1 * Nn1], g_L1dl[Nn1 * Nn1];
__device__ __nv_bfloat16 g_L1uh[Nn1 * Nn1], g_L1ul[Nn1 * Nn1];
__device__ __nv_bfloat16 g_B1h[Nn0 * Nn1],  g_B1l[Nn0 * Nn1];
__device__ __nv_bfloat16 g_B1th[Nn1 * Nn0], g_B1tl[Nn1 * Nn0];
__device__ __nv_bfloat16 g_B2h[Nn1 * Nn2],  g_B2l[Nn1 * Nn2];

// row-major bf16 A operands: X0 = [h0|p] (ld 256), X1 = [h1|q|h1|r] (ld 512)
__device__ __nv_bfloat16 g_X0qh[Nn0 * 256], g_X0ql[Nn0 * 256];
__device__ __nv_bfloat16 g_X1qh[Nn1 * 512], g_X1ql[Nn1 * 512];

// transposed bf16 buffers
__device__ __nv_bfloat16 g_bt0h[128 * Nn0],  g_bt0l[128 * Nn0];
__device__ __nv_bfloat16 g_bt1ah[128 * Nn1], g_bt1al[128 * Nn1];
__device__ __nv_bfloat16 g_bt2h[128 * Nn2],  g_bt2l[128 * Nn2];
__device__ __nv_bfloat16 g_bb0h[128 * Nn0],  g_bb0l[128 * Nn0];
__device__ __nv_bfloat16 g_bb1ah[128 * Nn1], g_bb1al[128 * Nn1];
__device__ __nv_bfloat16 g_bb1bh[128 * Nn1], g_bb1bl[128 * Nn1];

// combined Horner weights, transposed bf16 hi/lo
#define WSZ (2 * 128 * 128)
__device__ __nv_bfloat16 g_Wn0h[WSZ], g_Wn0l[WSZ];
__device__ __nv_bfloat16 g_Wn1h[WSZ], g_Wn1l[WSZ];
__device__ __nv_bfloat16 g_Wn2h[WSZ], g_Wn2l[WSZ];
__device__ __nv_bfloat16 g_Wm0h[WSZ], g_Wm0l[WSZ];   // layer-1 node weights
__device__ __nv_bfloat16 g_Wm1h[WSZ], g_Wm1l[WSZ];
__device__ __nv_bfloat16 g_Wm2h[WSZ], g_Wm2l[WSZ];
__device__ __nv_bfloat16 g_We0h[WSZ], g_We0l[WSZ];
__device__ __nv_bfloat16 g_WeD1h[WSZ], g_WeD1l[WSZ];
__device__ __nv_bfloat16 g_WeD2h[WSZ], g_WeD2l[WSZ];
__device__ __nv_bfloat16 g_WeU1h[WSZ], g_WeU1l[WSZ];
__device__ __nv_bfloat16 g_WeU2h[WSZ], g_WeU2l[WSZ];
__device__ __nv_bfloat16 g_Werh[128 * 128], g_Werl[128 * 128];

// ================= PTX helpers =================
__device__ __forceinline__ uint32_t smem_u32(const void* p) {
    uint32_t a;
    asm("{ .reg .u64 t; cvta.to.shared.u64 t, %1; cvt.u32.u64 %0, t; }" : "=r"(a) : "l"(p));
    return a;
}
__device__ __forceinline__ void ldsm_x4(uint32_t* r, uint32_t a) {
    asm volatile("ldmatrix.sync.aligned.m8n8.x4.shared.b16 {%0,%1,%2,%3}, [%4];"
                 : "=r"(r[0]), "=r"(r[1]), "=r"(r[2]), "=r"(r[3]) : "r"(a));
}
__device__ __forceinline__ void mma_bf16(float* c, const uint32_t* a, const uint32_t* b) {
    asm volatile(
        "mma.sync.aligned.m16n8k16.row.col.f32.bf16.bf16.f32 "
        "{%0,%1,%2,%3}, {%4,%5,%6,%7}, {%8,%9}, {%0,%1,%2,%3};"
        : "+f"(c[0]), "+f"(c[1]), "+f"(c[2]), "+f"(c[3])
        : "r"(a[0]), "r"(a[1]), "r"(a[2]), "r"(a[3]), "r"(b[0]), "r"(b[1]));
}
__device__ __forceinline__ void cp_async16(uint32_t dst, const void* src, int sz) {
    asm volatile("cp.async.cg.shared.global [%0], [%1], 16, %2;"
                 :: "r"(dst), "l"(src), "r"(sz));
}
__device__ __forceinline__ uint32_t sw_addr(uint32_t tile_base, int r, int chunk) {
    return tile_base + (uint32_t)(r * 64) + (uint32_t)((chunk ^ ((r >> 1) & 3)) << 4);
}

// ================= batched bf16x3 HMMA GEMM + fused epilogue =================
#define MM_SMEM (3 * 4 * 8192)
#define MAXJOB 14

struct MMJob {
    const __nv_bfloat16 *Ah, *Al, *Bh, *Bl;
    float* Cf;
    __nv_bfloat16 *Rh, *Rl;
    __nv_bfloat16 *Th, *Tl;
    int M, K, lda, ldb, ldc, ldR, ldT, tileStart, tilesX;
};
struct MMParams { MMJob j[MAXJOB]; int n; };

__global__ __launch_bounds__(256, 2)
void mmb_kernel(MMParams P)
{
    extern __shared__ __align__(128) char smem[];
    const uint32_t sbase = smem_u32(smem);
    const int tid = threadIdx.x, lane = tid & 31, wid = tid >> 5;
    const int wm = wid & 1, wn = wid >> 1;

    int bt = blockIdx.x;
    int ji = 0;
#pragma unroll 1
    while (ji + 1 < P.n && bt >= P.j[ji + 1].tileStart) ji++;
    const MMJob jb = P.j[ji];
    const int rel = bt - jb.tileStart;
    const int m0 = (rel % jb.tilesX) * 128;
    const int n0 = (rel / jb.tilesX) * 128;
    const int M = jb.M, K = jb.K, lda = jb.lda, ldb = jb.ldb;
    const int mrows = (M - m0 < 128) ? (M - m0) : 128;
    const __nv_bfloat16* Ah = jb.Ah + (size_t)m0 * lda;
    const __nv_bfloat16* Al = jb.Al + (size_t)m0 * lda;
    const __nv_bfloat16* Bh = jb.Bh + (size_t)n0 * ldb;
    const __nv_bfloat16* Bl = jb.Bl + (size_t)n0 * ldb;
    const int nk = (K + 31) >> 5;

    float acc[4][4][4];
#pragma unroll
    for (int i = 0; i < 4; i++)
#pragma unroll
        for (int j = 0; j < 4; j++)
#pragma unroll
            for (int v = 0; v < 4; v++) acc[i][j][v] = 0.f;

    auto load_stage = [&](int t) {
        const uint32_t sb = sbase + (uint32_t)(t % 3) * 32768;
        const int k0 = t << 5;
#pragma unroll
        for (int i = 0; i < 8; i++) {
            int idx = tid + i * 256;
            int tile = idx >> 9;
            int rem  = idx & 511;
            int r = rem >> 2, c = rem & 3;
            const __nv_bfloat16* gp;
            int ok;
            if (tile < 2) {
                gp = (tile == 0 ? Ah : Al) + (size_t)r * lda + k0 + c * 8;
                ok = (r < mrows) && (k0 + c * 8 < K);
            } else {
                gp = (tile == 2 ? Bh : Bl) + (size_t)r * ldb + k0 + c * 8;
                ok = (k0 + c * 8 < K);
            }
            cp_async16(sb + (uint32_t)tile * 8192 + sw_addr(0, r, c), gp, ok ? 16 : 0);
        }
    };

#pragma unroll
    for (int s = 0; s < 2; s++) {
        if (s < nk) load_stage(s);
        asm volatile("cp.async.commit_group;" ::: "memory");
    }

    const int frag_r = lane & 15;
    const int frag_c = lane >> 4;

    for (int t = 0; t < nk; t++) {
        asm volatile("cp.async.wait_group 1;" ::: "memory");
        __syncthreads();
        const uint32_t sb = sbase + (uint32_t)(t % 3) * 32768;
        const uint32_t tAh = sb, tAl = sb + 8192, tBh = sb + 16384, tBl = sb + 24576;

#pragma unroll
        for (int ks = 0; ks < 2; ks++) {
            const int ch = ks * 2 + frag_c;
            uint32_t bh[4][2], bl[4][2];
#pragma unroll
            for (int j = 0; j < 2; j++) {
                int r = wn * 32 + j * 16 + frag_r;
                uint32_t rr[4];
                ldsm_x4(rr, sw_addr(tBh, r, ch));
                bh[2 * j][0] = rr[0]; bh[2 * j][1] = rr[2];
                bh[2 * j + 1][0] = rr[1]; bh[2 * j + 1][1] = rr[3];
                ldsm_x4(rr, sw_addr(tBl, r, ch));
                bl[2 * j][0] = rr[0]; bl[2 * j][1] = rr[2];
                bl[2 * j + 1][0] = rr[1]; bl[2 * j + 1][1] = rr[3];
            }
#pragma unroll
            for (int mt = 0; mt < 4; mt++) {
                int r = wm * 64 + mt * 16 + frag_r;
                uint32_t ah[4], al[4];
                ldsm_x4(ah, sw_addr(tAh, r, ch));
                ldsm_x4(al, sw_addr(tAl, r, ch));
#pragma unroll
                for (int nt = 0; nt < 4; nt++) mma_bf16(acc[mt][nt], ah, bh[nt]);
#pragma unroll
                for (int nt = 0; nt < 4; nt++) mma_bf16(acc[mt][nt], ah, bl[nt]);
#pragma unroll
                for (int nt = 0; nt < 4; nt++) mma_bf16(acc[mt][nt], al, bh[nt]);
            }
        }
        if (t + 2 < nk) load_stage(t + 2);
        asm volatile("cp.async.commit_group;" ::: "memory");
    }

    // ---- fused epilogue: fp32 / row-bf16 / transposed-bf16 ----
    const int er = lane >> 2, ec = (lane & 3) * 2;
    const bool doBF = (jb.Rh != nullptr) || (jb.Th != nullptr);
#pragma unroll
    for (int mt = 0; mt < 4; mt++) {
        int r0 = m0 + wm * 64 + mt * 16 + er;
        int r1 = r0 + 8;
#pragma unroll
        for (int nt = 0; nt < 4; nt++) {
            int col = n0 + wn * 32 + nt * 8 + ec;
            float f0 = acc[mt][nt][0], f1 = acc[mt][nt][1];
            float f2 = acc[mt][nt][2], f3 = acc[mt][nt][3];
            if (jb.Cf) {
                if (r0 < M) *(float2*)&jb.Cf[(size_t)r0 * jb.ldc + col] = make_float2(f0, f1);
                if (r1 < M) *(float2*)&jb.Cf[(size_t)r1 * jb.ldc + col] = make_float2(f2, f3);
            }
            if (doBF) {
                __nv_bfloat16 h0 = __float2bfloat16(f0), h1 = __float2bfloat16(f1);
                __nv_bfloat16 h2 = __float2bfloat16(f2), h3 = __float2bfloat16(f3);
                __nv_bfloat16 l0 = __float2bfloat16(f0 - __bfloat162float(h0));
                __nv_bfloat16 l1 = __float2bfloat16(f1 - __bfloat162float(h1));
                __nv_bfloat16 l2 = __float2bfloat16(f2 - __bfloat162float(h2));
                __nv_bfloat16 l3 = __float2bfloat16(f3 - __bfloat162float(h3));
                if (jb.Rh) {
                    if (r0 < M) {
                        *(__nv_bfloat162*)&jb.Rh[(size_t)r0 * jb.ldR + col] = __halves2bfloat162(h0, h1);
                        *(__nv_bfloat162*)&jb.Rl[(size_t)r0 * jb.ldR + col] = __halves2bfloat162(l0, l1);
                    }
                    if (r1 < M) {
                        *(__nv_bfloat162*)&jb.Rh[(size_t)r1 * jb.ldR + col] = __halves2bfloat162(h2, h3);
                        *(__nv_bfloat162*)&jb.Rl[(size_t)r1 * jb.ldR + col] = __halves2bfloat162(l2, l3);
                    }
                }
                if (jb.Th) {
                    size_t cA = (size_t)col * jb.ldT, cB = (size_t)(col + 1) * jb.ldT;
                    if (r0 < M) {
                        jb.Th[cA + r0] = h0; jb.Th[cB + r0] = h1;
                        jb.Tl[cA + r0] = l0; jb.Tl[cB + r0] = l1;
                    }
                    if (r1 < M) {
                        jb.Th[cA + r1] = h2; jb.Th[cB + r1] = h3;
                        jb.Tl[cA + r1] = l2; jb.Tl[cB + r1] = l3;
                    }
                }
            }
        }
    }
}

// ================= reduce-convert =================
struct RJob {
    const float* base; int nP, pStride, M, N;
    __nv_bfloat16 *Rh, *Rl; int ldR;
    __nv_bfloat16 *Th, *Tl; int ldT;
    float* Cf; int ldc;
    int tileStart, tilesR;
};
struct RParams { RJob j[4]; int n; };

__global__ void rcvt_kernel(RParams P)
{
    __shared__ float tile[32][33];
    int b = blockIdx.x;
    int ji = 0;
#pragma unroll 1
    while (ji + 1 < P.n && b >= P.j[ji + 1].tileStart) ji++;
    const RJob jb = P.j[ji];
    int rel = b - jb.tileStart;
    int r0 = (rel % jb.tilesR) * 32, c0 = (rel / jb.tilesR) * 32;
    int tx = threadIdx.x, ty = threadIdx.y;
    for (int i = ty; i < 32; i += 8) {
        int r = r0 + i, c = c0 + tx;
        float v = 0.f;
        if (r < jb.M) {
            size_t off = (size_t)r * jb.N + c;
#pragma unroll 1
            for (int s = 0; s < jb.nP; s++) v += jb.base[off + (size_t)s * jb.pStride];
        }
        tile[i][tx] = v;
        if (r < jb.M) {
            if (jb.Cf) jb.Cf[(size_t)r * jb.ldc + c] = v;
            if (jb.Rh) {
                __nv_bfloat16 h = __float2bfloat16(v);
                jb.Rh[(size_t)r * jb.ldR + c] = h;
                jb.Rl[(size_t)r * jb.ldR + c] = __float2bfloat16(v - __bfloat162float(h));
            }
        }
    }
    __syncthreads();
    if (!jb.Th) return;
    for (int i = ty; i < 32; i += 8) {
        int c = c0 + i, r = r0 + tx;
        if (r < jb.M) {
            float v = tile[tx][i];
            __nv_bfloat16 h = __float2bfloat16(v);
            size_t idx = (size_t)c * jb.ldT + r;
            jb.Th[idx] = h;
            jb.Tl[idx] = __float2bfloat16(v - __bfloat162float(h));
        }
    }
}

// ================= operator split =================
struct SJob { const float* src; __nv_bfloat16 *dh, *dl; int n8, blkStart; };
struct SParams { SJob j[8]; int n; };

__global__ void splitb_kernel(SParams P)
{
    int b = blockIdx.x;
    int ji = 0;
#pragma unroll 1
    while (ji + 1 < P.n && b >= P.j[ji + 1].blkStart) ji++;
    const SJob jb = P.j[ji];
    int i = (b - jb.blkStart) * 256 + threadIdx.x;
    if (i >= jb.n8) return;
    float4 v0 = ((const float4*)jb.src)[i * 2];
    float4 v1 = ((const float4*)jb.src)[i * 2 + 1];
    __nv_bfloat162 h[4], l[4];
    h[0] = __floats2bfloat162_rn(v0.x, v0.y);
    h[1] = __floats2bfloat162_rn(v0.z, v0.w);
    h[2] = __floats2bfloat162_rn(v1.x, v1.y);
    h[3] = __floats2bfloat162_rn(v1.z, v1.w);
    l[0] = __floats2bfloat162_rn(v0.x - __bfloat162float(h[0].x), v0.y - __bfloat162float(h[0].y));
    l[1] = __floats2bfloat162_rn(v0.z - __bfloat162float(h[1].x), v0.w - __bfloat162float(h[1].y));
    l[2] = __floats2bfloat162_rn(v1.x - __bfloat162float(h[2].x), v1.y - __bfloat162float(h[2].y));
    l[3] = __floats2bfloat162_rn(v1.z - __bfloat162float(h[3].x), v1.w - __bfloat162float(h[3].y));
    ((uint4*)jb.dh)[i] = *(uint4*)h;
    ((uint4*)jb.dl)[i] = *(uint4*)l;
}

// ================= transpose-split (B1^T) =================
__global__ void tsplit1_kernel(const float* __restrict__ src,
                               __nv_bfloat16* __restrict__ dh, __nv_bfloat16* __restrict__ dl,
                               int lds, int rows, int cols, int tilesR)
{
    __shared__ float tile[32][33];
    int rel = blockIdx.x;
    int k0 = (rel % tilesR) * 32, n0 = (rel / tilesR) * 32;
    int tx = threadIdx.x, ty = threadIdx.y;
    for (int i = ty; i < 32; i += 8) {
        int k = k0 + i, n = n0 + tx;
        tile[i][tx] = (k < rows && n < cols) ? src[(size_t)k * lds + n] : 0.f;
    }
    __syncthreads();
    for (int i = ty; i < 32; i += 8) {
        int n = n0 + i, k = k0 + tx;
        if (n < cols && k < rows) {
            float v = tile[tx][i];
            __nv_bfloat16 h = __float2bfloat16(v);
            dh[(size_t)n * rows + k] = h;
            dl[(size_t)n * rows + k] = __float2bfloat16(v - __bfloat162float(h));
        }
    }
}

// ================= hconv =================
struct HJob {
    const float* src;
    __nv_bfloat16 *Rh, *Rl, *R2h, *R2l;
    __nv_bfloat16 *Th, *Tl;
    int rows, ldR, tileStart, tilesR;
};
struct HParams { HJob j[3]; int n; };

__global__ void hconv_kernel(HParams P)
{
    __shared__ float tile[32][33];
    int b = blockIdx.x;
    int ji = 0;
#pragma unroll 1
    while (ji + 1 < P.n && b >= P.j[ji + 1].tileStart) ji++;
    const HJob jb = P.j[ji];
    int rel = b - jb.tileStart;
    int r0 = (rel % jb.tilesR) * 32, c0 = (rel / jb.tilesR) * 32;
    int tx = threadIdx.x, ty = threadIdx.y;
    for (int i = ty; i < 32; i += 8) {
        int r = r0 + i, c = c0 + tx;
        float v = (r < jb.rows) ? jb.src[(size_t)r * CC + c] : 0.f;
        tile[i][tx] = v;
        if (r < jb.rows && jb.Rh) {
            __nv_bfloat16 h = __float2bfloat16(v);
            __nv_bfloat16 l = __float2bfloat16(v - __bfloat162float(h));
            jb.Rh[(size_t)r * jb.ldR + c] = h;
            jb.Rl[(size_t)r * jb.ldR + c] = l;
            if (jb.R2h) { jb.R2h[(size_t)r * jb.ldR + c] = h; jb.R2l[(size_t)r * jb.ldR + c] = l; }
        }
    }
    __syncthreads();
    if (!jb.Th) return;
    for (int i = ty; i < 32; i += 8) {
        int c = c0 + i, r = r0 + tx;
        if (r < jb.rows) {
            float v = tile[tx][i];
            __nv_bfloat16 h = __float2bfloat16(v);
            size_t idx = (size_t)c * jb.rows + r;
            jb.Th[idx] = h;
            jb.Tl[idx] = __float2bfloat16(v - __bfloat162float(h));
        }
    }
}

// ================= input linear =================
struct LJob { const float *x, *W, *b; float* y; int rows, rowStart; };
struct LParams { LJob j[3]; int n; };

__global__ void linb_kernel(LParams P)
{
    __shared__ float xs[CC];
    int b = blockIdx.x;
    int ji = 0;
#pragma unroll 1
    while (ji + 1 < P.n && b >= P.j[ji + 1].rowStart) ji++;
    const LJob jb = P.j[ji];
    int n = b - jb.rowStart, o = threadIdx.x;
    xs[o] = jb.x[(size_t)n * CC + o];
    __syncthreads();
    float acc = jb.b[o];
    const float* wr = &jb.W[(size_t)o * CC];
#pragma unroll 8
    for (int i = 0; i < CC; i++) acc += xs[i] * wr[i];
    jb.y[(size_t)n * CC + o] = acc;
}

// ================= Horner weight builder =================
struct WJob { const float* w; __nv_bfloat16 *dh, *dl; int korig, m0, m1, blkStart; };
struct WParams { WJob j[12]; int n; };

__global__ void wbuild_kernel(WParams P)
{
    int b = blockIdx.x;
    int ji = 0;
#pragma unroll 1
    while (ji + 1 < P.n && b >= P.j[ji + 1].blkStart) ji++;
    const WJob jb = P.j[ji];
    int rel = b - jb.blkStart;
    int s = rel >> 7, o = rel & 127;
    int i = threadIdx.x;
    int S = (jb.m1 == -2) ? 1 : 2;
    int k = (s == 0) ? jb.m0 : jb.m1;
    float v = (k >= 0) ? jb.w[((size_t)i * CC + o) * jb.korig + k] : 0.f;
    __nv_bfloat16 h = __float2bfloat16(v);
    size_t idx = (size_t)o * (S * 128) + s * 128 + i;
    jb.dh[idx] = h;
    jb.dl[idx] = __float2bfloat16(v - __bfloat162float(h));
}

__global__ void head_kernel(const float* __restrict__ h0, const float* __restrict__ ow,
                            const float* __restrict__ ob, float* __restrict__ out, int total)
{
    int idx = blockIdx.x * blockDim.x + threadIdx.x;
    if (idx >= total) return;
    int n = idx >> 1, c = idx & 1;
    float acc = ob[c];
    const float* hr = &h0[(size_t)n * CC];
    const float* wr = &ow[(size_t)c * CC];
#pragma unroll 8
    for (int i = 0; i < CC; i++) acc += hr[i] * wr[i];
    out[idx] = 1.f / (1.f + expf(-acc));
}

// ================= host-side builders =================
struct MMBatch { MMParams p; int tiles; };
static void mmAdd(MMBatch& b,
                  const __nv_bfloat16* Ah, const __nv_bfloat16* Al, int lda,
                  const __nv_bfloat16* Bh, const __nv_bfloat16* Bl, int ldb,
                  int M, int N, int K,
                  float* Cf, int ldc,
                  __nv_bfloat16* Rh = nullptr, __nv_bfloat16* Rl = nullptr, int ldR = 0,
                  __nv_bfloat16* Th = nullptr, __nv_bfloat16* Tl = nullptr, int ldT = 0)
{
    MMJob& j = b.p.j[b.p.n++];
    j.Ah = Ah; j.Al = Al; j.Bh = Bh; j.Bl = Bl;
    j.Cf = Cf; j.Rh = Rh; j.Rl = Rl; j.Th = Th; j.Tl = Tl;
    j.M = M; j.K = K; j.lda = lda; j.ldb = ldb; j.ldc = ldc; j.ldR = ldR; j.ldT = ldT;
    j.tileStart = b.tiles; j.tilesX = (M + 127) / 128;
    b.tiles += j.tilesX * (N / 128);
}
static void mmAddSplit(MMBatch& b,
                       const __nv_bfloat16* Ah, const __nv_bfloat16* Al, int lda,
                       const __nv_bfloat16* Bh, const __nv_bfloat16* Bl, int ldb,
                       int M, int N, int K, int nsp, float* part)
{
    int chunk = (((K + nsp - 1) / nsp) + 7) & ~7;
    for (int s = 0; s < nsp; s++) {
        int k0 = s * chunk;
        int kl = (K - k0 < chunk) ? (K - k0) : chunk;
        mmAdd(b, Ah + k0, Al + k0, lda, Bh + k0, Bl + k0, ldb, M, N, kl,
              part + (size_t)s * M * N, N);
    }
}
static void mmRun(MMBatch& b)
{
    if (b.p.n) mmb_kernel<<<b.tiles, 256, MM_SMEM>>>(b.p);
    b.p.n = 0; b.tiles = 0;
}

struct RBatch { RParams p; int tiles; };
static void rAdd(RBatch& b, const float* base, int nP, int M, int N,
                 __nv_bfloat16* Rh, __nv_bfloat16* Rl, int ldR,
                 __nv_bfloat16* Th, __nv_bfloat16* Tl, int ldT,
                 float* Cf = nullptr, int ldc = 0)
{
    RJob& j = b.p.j[b.p.n++];
    j.base = base; j.nP = nP; j.pStride = M * N; j.M = M; j.N = N;
    j.Rh = Rh; j.Rl = Rl; j.ldR = ldR; j.Th = Th; j.Tl = Tl; j.ldT = ldT;
    j.Cf = Cf; j.ldc = ldc;
    j.tileStart = b.tiles; j.tilesR = (M + 31) / 32;
    b.tiles += j.tilesR * (N / 32);
}
static void rRun(RBatch& b)
{
    if (b.p.n) rcvt_kernel<<<b.tiles, dim3(32, 8)>>>(b.p);
    b.p.n = 0; b.tiles = 0;
}

#define SYM(v, g) { void* p_; cudaGetSymbolAddress(&p_, g); v = (decltype(v))p_; }

extern "C" void kernel_launch(void* const* d_in, const int* in_sizes, int n_in,
                              void* d_out, int out_size)
{
    (void)in_sizes; (void)n_in; (void)out_size;
    const float* x0    = (const float*)d_in[0];
    const float* x1    = (const float*)d_in[1];
    const float* x2    = (const float*)d_in[2];
    const float* L0    = (const float*)d_in[3];
    const float* L1d   = (const float*)d_in[4];
    const float* L1u   = (const float*)d_in[5];
    const float* B1    = (const float*)d_in[8];
    const float* B2    = (const float*)d_in[9];
    const float* in_w0 = (const float*)d_in[10];
    const float* in_b0 = (const float*)d_in[11];
    const float* in_w1 = (const float*)d_in[12];
    const float* in_b1 = (const float*)d_in[13];
    const float* in_w2 = (const float*)d_in[14];
    const float* in_b2 = (const float*)d_in[15];
    const float* l0_w0 = (const float*)d_in[16];
    const float* l0_w1 = (const float*)d_in[17];
    const float* l1_w0 = (const float*)d_in[19];
    const float* out_w = (const float*)d_in[22];
    const float* out_b = (const float*)d_in[23];
    float* out = (float*)d_out;

    cudaFuncSetAttribute(mmb_kernel, cudaFuncAttributeMaxDynamicSharedMemorySize, MM_SMEM);

    float *h0, *h1, *h2, *pool;
    SYM(h0, g_h0); SYM(h1, g_h1); SYM(h2, g_h2); SYM(pool, g_part);
    __nv_bfloat16 *L0h, *L0l, *L1dh, *L1dl, *L1uh, *L1ul;
    __nv_bfloat16 *B1h, *B1l, *B1th, *B1tl, *B2h, *B2l;
    SYM(L0h, g_L0h); SYM(L0l, g_L0l);
    SYM(L1dh, g_L1dh); SYM(L1dl, g_L1dl); SYM(L1uh, g_L1uh); SYM(L1ul, g_L1ul);
    SYM(B1h, g_B1h); SYM(B1l, g_B1l); SYM(B1th, g_B1th); SYM(B1tl, g_B1tl);
    SYM(B2h, g_B2h); SYM(B2l, g_B2l);
    __nv_bfloat16 *X0qh, *X0ql, *X1qh, *X1ql;
    SYM(X0qh, g_X0qh); SYM(X0ql, g_X0ql); SYM(X1qh, g_X1qh); SYM(X1ql, g_X1ql);
    __nv_bfloat16 *bt0h, *bt0l, *bt1ah, *bt1al, *bt2h, *bt2l;
    SYM(bt0h, g_bt0h); SYM(bt0l, g_bt0l);
    SYM(bt1ah, g_bt1ah); SYM(bt1al, g_bt1al);
    SYM(bt2h, g_bt2h); SYM(bt2l, g_bt2l);
    __nv_bfloat16 *bb0h, *bb0l, *bb1ah, *bb1al, *bb1bh, *bb1bl;
    SYM(bb0h, g_bb0h); SYM(bb0l, g_bb0l);
    SYM(bb1ah, g_bb1ah); SYM(bb1al, g_bb1al);
    SYM(bb1bh, g_bb1bh); SYM(bb1bl, g_bb1bl);
    __nv_bfloat16 *Wn0h, *Wn0l, *Wn1h, *Wn1l, *Wn2h, *Wn2l;
    __nv_bfloat16 *Wm0h, *Wm0l, *Wm1h, *Wm1l, *Wm2h, *Wm2l;
    __nv_bfloat16 *We0h, *We0l, *WeD1h, *WeD1l, *WeD2h, *WeD2l;
    __nv_bfloat16 *WeU1h, *WeU1l, *WeU2h, *WeU2l, *Werh, *Werl;
    SYM(Wn0h, g_Wn0h); SYM(Wn0l, g_Wn0l);
    SYM(Wn1h, g_Wn1h); SYM(Wn1l, g_Wn1l);
    SYM(Wn2h, g_Wn2h); SYM(Wn2l, g_Wn2l);
    SYM(Wm0h, g_Wm0h); SYM(Wm0l, g_Wm0l);
    SYM(Wm1h, g_Wm1h); SYM(Wm1l, g_Wm1l);
    SYM(Wm2h, g_Wm2h); SYM(Wm2l, g_Wm2l);
    SYM(We0h, g_We0h); SYM(We0l, g_We0l);
    SYM(WeD1h, g_WeD1h); SYM(WeD1l, g_WeD1l);
    SYM(WeD2h, g_WeD2h); SYM(WeD2l, g_WeD2l);
    SYM(WeU1h, g_WeU1h); SYM(WeU1l, g_WeU1l);
    SYM(WeU2h, g_WeU2h); SYM(WeU2l, g_WeU2l);
    SYM(Werh, g_Werh); SYM(Werl, g_Werl);

    const size_t SZ0 = (size_t)Nn0 * 128, SZ1 = (size_t)Nn1 * 128;
    // pool layout (floats)
    const size_t OFF_Pp = 0;           // 4*SZ0
    const size_t OFF_Pq = 1100000;     // 2*SZ1
    const size_t OFF_Pr = 2700000;     // 3*SZ1
    // Phase B: H1 (10 slots: D0-3,U4-7,We0=8,Wer=9), H0 (4: L0 0-2, base 3)
    const size_t OFF_H1 = 0;           // 10*SZ1 = 7.68M
    const size_t OFF_H0 = 7700000;     // 4*SZ0 = 1.02M
    // P6 pools PD/PU (5 slots: splits 0-3, u 4), PN (4: splits 0-2, u 3)
    const size_t OFF_PD = 8800000;     // 5*SZ1 = 3.84M
    const size_t OFF_PU = 12700000;    // 5*SZ1
    const size_t OFF_PN = 16600000;    // 4*SZ0
    // Phase C (layer 1)
    const size_t OFF_L1P = 0;          // 10*SZ0 = 2.56M
    const size_t OFF_R1 = 2600000;     // 9*SZ0 = 2.30M
    const size_t OFF_R2 = 5000000;     // 9*SZ0
    const int SPL1 = 10, SPL0 = 8;     // layer-1 split counts

    MMBatch mb = {}; RBatch rb = {};

    // ---- operator splits ----
    {
        SParams sp = {};
        int blks = 0;
        auto add = [&](const float* s, __nv_bfloat16* dh, __nv_bfloat16* dl, size_t cnt) {
            SJob& j = sp.j[sp.n++];
            j.src = s; j.dh = dh; j.dl = dl; j.n8 = (int)(cnt / 8); j.blkStart = blks;
            blks += (j.n8 + 255) / 256;
        };
        add(L1d, L1dh, L1dl, (size_t)Nn1 * Nn1);
        add(L1u, L1uh, L1ul, (size_t)Nn1 * Nn1);
        add(B1,  B1h,  B1l,  (size_t)Nn0 * Nn1);
        add(B2,  B2h,  B2l,  (size_t)Nn1 * Nn2);
        add(L0,  L0h,  L0l,  (size_t)Nn0 * Nn0);
        splitb_kernel<<<blks, 256>>>(sp);
    }
    tsplit1_kernel<<<((Nn0 + 31) / 32) * ((Nn1 + 31) / 32), dim3(32, 8)>>>(
        B1, B1th, B1tl, Nn1, Nn0, Nn1, (Nn0 + 31) / 32);

    // ---- input linears ----
    {
        LParams lp = {};
        lp.j[0] = { x0, in_w0, in_b0, h0, Nn0, 0 };
        lp.j[1] = { x1, in_w1, in_b1, h1, Nn1, Nn0 };
        lp.j[2] = { x2, in_w2, in_b2, h2, Nn2, Nn0 + Nn1 };
        lp.n = 3;
        linb_kernel<<<Nn0 + Nn1 + Nn2, CC>>>(lp);
    }

    // ---- ALL Horner weights (both layers, one launch) ----
    {
        WParams wp = {};
        int blk = 0;
        auto add = [&](const float* w, __nv_bfloat16* dh, __nv_bfloat16* dl,
                       int korig, int m0, int m1) {
            WJob& j = wp.j[wp.n++];
            j.w = w; j.dh = dh; j.dl = dl; j.korig = korig; j.m0 = m0; j.m1 = m1;
            j.blkStart = blk;
            blk += ((m1 == -2) ? 1 : 2) * 128;
        };
        add(l0_w0, Wn0h, Wn0l, 6, 0, 3);
        add(l0_w0, Wn1h, Wn1l, 6, 1, 4);
        add(l0_w0, Wn2h, Wn2l, 6, 2, 5);
        add(l0_w1, We0h, We0l, 11, 0, 5);
        add(l0_w1, WeD1h, WeD1l, 11, 1, 6);
        add(l0_w1, WeD2h, WeD2l, 11, 2, 7);
        add(l0_w1, WeU1h, WeU1l, 11, 3, 9);
        add(l0_w1, WeU2h, WeU2l, 11, 4, 10);
        add(l0_w1, Werh, Werl, 11, 8, -2);
        add(l1_w0, Wm0h, Wm0l, 6, 0, 3);
        add(l1_w0, Wm1h, Wm1l, 6, 1, 4);
        add(l1_w0, Wm2h, Wm2l, 6, 2, 5);
        wbuild_kernel<<<blk, 128>>>(wp);
    }

    // ---- hconv ----
    {
        HParams hp = {};
        int tiles = 0;
        int tr0 = (Nn0 + 31) / 32, tr1 = (Nn1 + 31) / 32, tr2 = (Nn2 + 31) / 32;
        hp.j[0] = { h0, X0qh, X0ql, nullptr, nullptr, bt0h, bt0l, Nn0, 256, tiles, tr0 };
        tiles += tr0 * 4;
        hp.j[1] = { h1, X1qh, X1ql, X1qh + 256, X1ql + 256, bt1ah, bt1al, Nn1, 512, tiles, tr1 };
        tiles += tr1 * 4;
        hp.j[2] = { h2, nullptr, nullptr, nullptr, nullptr, bt2h, bt2l, Nn2, 0, tiles, tr2 };
        tiles += tr2 * 4;
        hp.n = 3;
        hconv_kernel<<<tiles, dim3(32, 8)>>>(hp);
    }

    // P2: projections
    mmAddSplit(mb, B1h,  B1l,  Nn1, bt1ah, bt1al, Nn1, Nn0, 128, Nn1, 4, pool + OFF_Pp);
    mmAddSplit(mb, B2h,  B2l,  Nn2, bt2h,  bt2l,  Nn2, Nn1, 128, Nn2, 3, pool + OFF_Pr);
    mmAddSplit(mb, B1th, B1tl, Nn0, bt0h,  bt0l,  Nn0, Nn1, 128, Nn0, 2, pool + OFF_Pq);
    mmRun(mb);
    rAdd(rb, pool + OFF_Pp, 4, Nn0, 128, X0qh + 128, X0ql + 128, 256, nullptr, nullptr, 0);
    rAdd(rb, pool + OFF_Pr, 3, Nn1, 128, X1qh + 384, X1ql + 384, 512, nullptr, nullptr, 0);
    rAdd(rb, pool + OFF_Pq, 2, Nn1, 128, X1qh + 128, X1ql + 128, 512, nullptr, nullptr, 0);
    rRun(rb);

    // P4: ALL channel mixes. Inner -> T-epilogue; u-terms/bases -> pool slots.
    mmAdd(mb, X1qh, X1ql, 512, WeD2h, WeD2l, 256, Nn1, 128, 256,
          nullptr, 0, nullptr, nullptr, 0, bb1ah, bb1al, Nn1);
    mmAdd(mb, X1qh + 256, X1ql + 256, 512, WeU2h, WeU2l, 256, Nn1, 128, 256,
          nullptr, 0, nullptr, nullptr, 0, bb1bh, bb1bl, Nn1);
    mmAdd(mb, X0qh, X0ql, 256, Wn2h, Wn2l, 256, Nn0, 128, 256,
          nullptr, 0, nullptr, nullptr, 0, bb0h, bb0l, Nn0);
    mmAdd(mb, X1qh, X1ql, 512, WeD1h, WeD1l, 256, Nn1, 128, 256, pool + OFF_PD + 4 * SZ1, 128);
    mmAdd(mb, X1qh + 256, X1ql + 256, 512, WeU1h, WeU1l, 256, Nn1, 128, 256, pool + OFF_PU + 4 * SZ1, 128);
    mmAdd(mb, X0qh, X0ql, 256, Wn1h, Wn1l, 256, Nn0, 128, 256, pool + OFF_PN + 3 * SZ0, 128);
    mmAdd(mb, X1qh, X1ql, 512, We0h, We0l, 256, Nn1, 128, 256, pool + OFF_H1 + 8 * SZ1, 128);
    mmAdd(mb, X1qh + 384, X1ql + 384, 512, Werh, Werl, 128, Nn1, 128, 128, pool + OFF_H1 + 9 * SZ1, 128);
    mmAdd(mb, X0qh, X0ql, 256, Wn0h, Wn0l, 256, Nn0, 128, 256, pool + OFF_H0 + 3 * SZ0, 128);
    mmRun(mb);

    // P6: first Horner hops (R13 split config: 4/4/3)
    mmAddSplit(mb, L1dh, L1dl, Nn1, bb1ah, bb1al, Nn1, Nn1, 128, Nn1, 4, pool + OFF_PD);
    mmAddSplit(mb, L1uh, L1ul, Nn1, bb1bh, bb1bl, Nn1, Nn1, 128, Nn1, 4, pool + OFF_PU);
    mmAddSplit(mb, L0h,  L0l,  Nn0, bb0h,  bb0l,  Nn0, Nn0, 128, Nn0, 3, pool + OFF_PN);
    mmRun(mb);
    rAdd(rb, pool + OFF_PD, 5, Nn1, 128, nullptr, nullptr, 0, bb1ah, bb1al, Nn1);
    rAdd(rb, pool + OFF_PU, 5, Nn1, 128, nullptr, nullptr, 0, bb1bh, bb1bl, Nn1);
    rAdd(rb, pool + OFF_PN, 4, Nn0, 128, nullptr, nullptr, 0, bb0h, bb0l, Nn0);
    rRun(rb);

    // P8: second Horner hops
    mmAddSplit(mb, L1dh, L1dl, Nn1, bb1ah, bb1al, Nn1, Nn1, 128, Nn1, 4, pool + OFF_H1);
    mmAddSplit(mb, L1uh, L1ul, Nn1, bb1bh, bb1bl, Nn1, Nn1, 128, Nn1, 4, pool + OFF_H1 + 4 * SZ1);
    mmAddSplit(mb, L0h,  L0l,  Nn0, bb0h,  bb0l,  Nn0, Nn0, 128, Nn0, 3, pool + OFF_H0);
    mmRun(mb);

    // h1' (transposed) and h0' (row)
    rAdd(rb, pool + OFF_H1, 10, Nn1, 128, nullptr, nullptr, 0, bt1ah, bt1al, Nn1);
    rAdd(rb, pool + OFF_H0, 4, Nn0, 128, X0qh, X0ql, 256, nullptr, nullptr, 0);
    rRun(rb);

    // ============ LAYER 1 (deep split-K: underfilled stages) ============
    // p' = B1 @ h1'
    mmAddSplit(mb, B1h, B1l, Nn1, bt1ah, bt1al, Nn1, Nn0, 128, Nn1, SPL1, pool + OFF_L1P);
    mmRun(mb);
    rAdd(rb, pool + OFF_L1P, SPL1, Nn0, 128, X0qh + 128, X0ql + 128, 256, nullptr, nullptr, 0);
    rRun(rb);

    // inner (T-epi) + u-term + base in one launch
    mmAdd(mb, X0qh, X0ql, 256, Wm2h, Wm2l, 256, Nn0, 128, 256,
          nullptr, 0, nullptr, nullptr, 0, bb0h, bb0l, Nn0);
    mmAdd(mb, X0qh, X0ql, 256, Wm1h, Wm1l, 256, Nn0, 128, 256, pool + OFF_R1 + SPL0 * SZ0, 128);
    mmAdd(mb, X0qh, X0ql, 256, Wm0h, Wm0l, 256, Nn0, 128, 256, pool + OFF_R2 + SPL0 * SZ0, 128);
    mmRun(mb);

    // hop1 + u
    mmAddSplit(mb, L0h, L0l, Nn0, bb0h, bb0l, Nn0, Nn0, 128, Nn0, SPL0, pool + OFF_R1);
    mmRun(mb);
    rAdd(rb, pool + OFF_R1, SPL0 + 1, Nn0, 128, nullptr, nullptr, 0, bb0h, bb0l, Nn0);
    rRun(rb);

    // hop2 + base -> fp32 h0''
    mmAddSplit(mb, L0h, L0l, Nn0, bb0h, bb0l, Nn0, Nn0, 128, Nn0, SPL0, pool + OFF_R2);
    mmRun(mb);
    rAdd(rb, pool + OFF_R2, SPL0 + 1, Nn0, 128, nullptr, nullptr, 0, nullptr, nullptr, 0, h0, 128);
    rRun(rb);

    head_kernel<<<(Nn0 * 2 + 255) / 256, 256>>>(h0, out_w, out_b, out, Nn0 * 2);
}